// round 10
// baseline (speedup 1.0000x reference)
#include <cuda_runtime.h>

#define N_B    64
#define T_LEN  2048
#define IN_D   8
#define C_CH   2
#define STEPS  2047
#define LCHUNK 16
#define NCHUNK 128           // 128*16 = 2048 >= 2047
#define WPB    4
#define NCHAIN (N_B * C_CH)          // 128
#define NWARPS (NCHAIN * NCHUNK)     // 16384
#define FULLM  0xffffffffu

__device__ __align__(16) float g_part [NWARPS * 100];
__device__ __align__(16) float g_part2[NCHAIN * 16 * 100];

// ---------------------------------------------------------------------------
// Kernel 1: one warp per (chain, chunk). Order-7 Taylor expm of skew G.
// Entire step loop is register + shuffle only: tiles live distributed across
// 25 lanes (lane l = (j2=l/5, k2=l%5) owns the 2x2 tile at rows 2*j2,
// cols 2*k2); row-strips are gathered from tiles by warp shuffle.
// No shared memory, no __syncwarp in the loop.
// ---------------------------------------------------------------------------
__global__ void __launch_bounds__(128) step_kernel(const float* __restrict__ x,
                                                   const float* __restrict__ A) {
    __shared__ float sk[C_CH * IN_D * 100];
    __shared__ float xs[WPB][(LCHUNK + 1) * IN_D];
    __shared__ __align__(16) float dxs[WPB][LCHUNK * IN_D];

    int tid = threadIdx.x;

    // skew = A - A^T
    for (int idx = tid; idx < C_CH * IN_D * 100; idx += 128) {
        int jk = idx % 100, ci = idx / 100;
        int j = jk / 10, k = jk % 10;
        sk[idx] = A[ci * 100 + j * 10 + k] - A[ci * 100 + k * 10 + j];
    }

    int warp = tid >> 5, lane = tid & 31;
    int w     = blockIdx.x * WPB + warp;     // [0, 16384)
    int chunk = w & (NCHUNK - 1);
    int chain = w >> 7;
    int c     = chain & 1;
    int n     = chain >> 1;
    int t0    = chunk * LCHUNK;
    int nsteps = min(LCHUNK, STEPS - t0);

    const float* xp = x + ((size_t)n * T_LEN + t0) * IN_D;
    float* xw = xs[warp];
    int cnt = (nsteps + 1) * IN_D;
    for (int idx = lane; idx < cnt; idx += 32) xw[idx] = xp[idx];
    __syncthreads();                          // sk + xw ready

    float* dxp = dxs[warp];
    for (int idx = lane; idx < nsteps * IN_D; idx += 32)
        dxp[idx] = xw[idx + IN_D] - xw[idx];
    __syncwarp();                             // dx ready (only sync needed)

    bool act = lane < 25;
    int l  = act ? lane : 24;
    int j2 = l / 5, k2 = l % 5;
    int r0 = 2 * j2, c0 = 2 * k2;
    float dI = (j2 == k2) ? 1.f : 0.f;

    // shuffle source lanes (registers, loop-invariant)
    int srcR[5], srcC[5];
#pragma unroll
    for (int i = 0; i < 5; ++i) { srcR[i] = j2 * 5 + i; srcC[i] = i * 5 + k2; }

    // skew tiles -> registers
    const float* skc = sk + c * IN_D * 100;
    float ska[IN_D][4];
#pragma unroll
    for (int i = 0; i < IN_D; ++i) {
        float2 a0 = *(const float2*)(skc + i * 100 + r0 * 10 + c0);
        float2 a1 = *(const float2*)(skc + i * 100 + r0 * 10 + 10 + c0);
        ska[i][0] = a0.x; ska[i][1] = a0.y; ska[i][2] = a1.x; ska[i][3] = a1.y;
    }

    const float c2 = 0.5f,      c4 = 1.f / 24.f,  c6 = 1.f / 720.f;
    const float s2 = 1.f / 6.f, s4 = 1.f / 120.f, s6 = 1.f / 5040.f;

    // Acc tile (register-distributed)
    float ac00 = dI, ac01 = 0.f, ac10 = 0.f, ac11 = dI;

    float Gr0[10], Gr1[10], Wr0[10], Wr1[10];

    for (int t = 0; t < nsteps; ++t) {
        // ---- G tile ----
        const float* d = dxp + t * IN_D;
        float4 dA4 = *(const float4*)(d);
        float4 dB4 = *(const float4*)(d + 4);
        float dv[8] = {dA4.x, dA4.y, dA4.z, dA4.w, dB4.x, dB4.y, dB4.z, dB4.w};
        float g00 = 0.f, g01 = 0.f, g10 = 0.f, g11 = 0.f;
#pragma unroll
        for (int i = 0; i < 8; ++i) {
            g00 = fmaf(dv[i], ska[i][0], g00); g01 = fmaf(dv[i], ska[i][1], g01);
            g10 = fmaf(dv[i], ska[i][2], g10); g11 = fmaf(dv[i], ska[i][3], g11);
        }

        // ---- G strips from tiles (20 SHFL) ----
#pragma unroll
        for (int k = 0; k < 5; ++k) {
            Gr0[2*k]   = __shfl_sync(FULLM, g00, srcR[k]);
            Gr0[2*k+1] = __shfl_sync(FULLM, g01, srcR[k]);
            Gr1[2*k]   = __shfl_sync(FULLM, g10, srcR[k]);
            Gr1[2*k+1] = __shfl_sync(FULLM, g11, srcR[k]);
        }

        // ---- W = G@G (A strips, B tiles via SHFL) ----
        float w00 = 0.f, w01 = 0.f, w10 = 0.f, w11 = 0.f;
#pragma unroll
        for (int i = 0; i < 5; ++i) {
            float b00 = __shfl_sync(FULLM, g00, srcC[i]);
            float b01 = __shfl_sync(FULLM, g01, srcC[i]);
            float b10 = __shfl_sync(FULLM, g10, srcC[i]);
            float b11 = __shfl_sync(FULLM, g11, srcC[i]);
            float a00 = Gr0[2*i], a01 = Gr0[2*i+1], a10 = Gr1[2*i], a11 = Gr1[2*i+1];
            w00 = fmaf(a00, b00, w00); w00 = fmaf(a01, b10, w00);
            w01 = fmaf(a00, b01, w01); w01 = fmaf(a01, b11, w01);
            w10 = fmaf(a10, b00, w10); w10 = fmaf(a11, b10, w10);
            w11 = fmaf(a10, b01, w11); w11 = fmaf(a11, b11, w11);
        }

        // ---- W strips from tiles (20 SHFL) ----
#pragma unroll
        for (int k = 0; k < 5; ++k) {
            Wr0[2*k]   = __shfl_sync(FULLM, w00, srcR[k]);
            Wr0[2*k+1] = __shfl_sync(FULLM, w01, srcR[k]);
            Wr1[2*k]   = __shfl_sync(FULLM, w10, srcR[k]);
            Wr1[2*k+1] = __shfl_sync(FULLM, w11, srcR[k]);
        }

        // ---- P = W@W ----
        float p00 = 0.f, p01 = 0.f, p10 = 0.f, p11 = 0.f;
#pragma unroll
        for (int i = 0; i < 5; ++i) {
            float b00 = __shfl_sync(FULLM, w00, srcC[i]);
            float b01 = __shfl_sync(FULLM, w01, srcC[i]);
            float b10 = __shfl_sync(FULLM, w10, srcC[i]);
            float b11 = __shfl_sync(FULLM, w11, srcC[i]);
            float a00 = Wr0[2*i], a01 = Wr0[2*i+1], a10 = Wr1[2*i], a11 = Wr1[2*i+1];
            p00 = fmaf(a00, b00, p00); p00 = fmaf(a01, b10, p00);
            p01 = fmaf(a00, b01, p01); p01 = fmaf(a01, b11, p01);
            p10 = fmaf(a10, b00, p10); p10 = fmaf(a11, b10, p10);
            p11 = fmaf(a10, b01, p11); p11 = fmaf(a11, b11, p11);
        }

        // low-order C,S folds
        float C00 = fmaf(c4, p00, fmaf(c2, w00, dI));
        float C01 = fmaf(c4, p01, c2 * w01);
        float C10 = fmaf(c4, p10, c2 * w10);
        float C11 = fmaf(c4, p11, fmaf(c2, w11, dI));
        float S00 = fmaf(s4, p00, fmaf(s2, w00, dI));
        float S01 = fmaf(s4, p01, s2 * w01);
        float S10 = fmaf(s4, p10, s2 * w10);
        float S11 = fmaf(s4, p11, fmaf(s2, w11, dI));

        // ---- V6 = W@P ----
        float v00 = 0.f, v01 = 0.f, v10 = 0.f, v11 = 0.f;
#pragma unroll
        for (int i = 0; i < 5; ++i) {
            float b00 = __shfl_sync(FULLM, p00, srcC[i]);
            float b01 = __shfl_sync(FULLM, p01, srcC[i]);
            float b10 = __shfl_sync(FULLM, p10, srcC[i]);
            float b11 = __shfl_sync(FULLM, p11, srcC[i]);
            float a00 = Wr0[2*i], a01 = Wr0[2*i+1], a10 = Wr1[2*i], a11 = Wr1[2*i+1];
            v00 = fmaf(a00, b00, v00); v00 = fmaf(a01, b10, v00);
            v01 = fmaf(a00, b01, v01); v01 = fmaf(a01, b11, v01);
            v10 = fmaf(a10, b00, v10); v10 = fmaf(a11, b10, v10);
            v11 = fmaf(a10, b01, v11); v11 = fmaf(a11, b11, v11);
        }
        C00 = fmaf(c6, v00, C00); C01 = fmaf(c6, v01, C01);
        C10 = fmaf(c6, v10, C10); C11 = fmaf(c6, v11, C11);
        S00 = fmaf(s6, v00, S00); S01 = fmaf(s6, v01, S01);
        S10 = fmaf(s6, v10, S10); S11 = fmaf(s6, v11, S11);

        // ---- E = C + G@S ----
        float e00 = C00, e01 = C01, e10 = C10, e11 = C11;
#pragma unroll
        for (int i = 0; i < 5; ++i) {
            float b00 = __shfl_sync(FULLM, S00, srcC[i]);
            float b01 = __shfl_sync(FULLM, S01, srcC[i]);
            float b10 = __shfl_sync(FULLM, S10, srcC[i]);
            float b11 = __shfl_sync(FULLM, S11, srcC[i]);
            float a00 = Gr0[2*i], a01 = Gr0[2*i+1], a10 = Gr1[2*i], a11 = Gr1[2*i+1];
            e00 = fmaf(a00, b00, e00); e00 = fmaf(a01, b10, e00);
            e01 = fmaf(a00, b01, e01); e01 = fmaf(a01, b11, e01);
            e10 = fmaf(a10, b00, e10); e10 = fmaf(a11, b10, e10);
            e11 = fmaf(a10, b01, e11); e11 = fmaf(a11, b11, e11);
        }

        // ---- Acc = Acc @ E ----
        float na00 = 0.f, na01 = 0.f, na10 = 0.f, na11 = 0.f;
#pragma unroll
        for (int i = 0; i < 5; ++i) {
            float a00 = __shfl_sync(FULLM, ac00, srcR[i]);
            float a01 = __shfl_sync(FULLM, ac01, srcR[i]);
            float a10 = __shfl_sync(FULLM, ac10, srcR[i]);
            float a11 = __shfl_sync(FULLM, ac11, srcR[i]);
            float b00 = __shfl_sync(FULLM, e00, srcC[i]);
            float b01 = __shfl_sync(FULLM, e01, srcC[i]);
            float b10 = __shfl_sync(FULLM, e10, srcC[i]);
            float b11 = __shfl_sync(FULLM, e11, srcC[i]);
            na00 = fmaf(a00, b00, na00); na00 = fmaf(a01, b10, na00);
            na01 = fmaf(a00, b01, na01); na01 = fmaf(a01, b11, na01);
            na10 = fmaf(a10, b00, na10); na10 = fmaf(a11, b10, na10);
            na11 = fmaf(a10, b01, na11); na11 = fmaf(a11, b11, na11);
        }
        ac00 = na00; ac01 = na01; ac10 = na10; ac11 = na11;
    }

    if (act) {
        float* pp = g_part + (size_t)w * 100;
        *(float2*)(pp + r0 * 10 + c0)       = make_float2(ac00, ac01);
        *(float2*)(pp + (r0 + 1) * 10 + c0) = make_float2(ac10, ac11);
    }
}

// ---------------------------------------------------------------------------
// Tree combine: 128 partials -> 16 (combineA, 8-way) -> 1 (combineB, 16-way)
// ---------------------------------------------------------------------------
__device__ __forceinline__ void cmm22(const float* __restrict__ Am,
                                      const float* __restrict__ Bm,
                                      int r0, int c0,
                                      float& o00, float& o01, float& o10, float& o11) {
    o00 = 0.f; o01 = 0.f; o10 = 0.f; o11 = 0.f;
#pragma unroll
    for (int i = 0; i < 10; i += 2) {
        float2 a0 = *(const float2*)(Am + r0 * 10 + i);
        float2 a1 = *(const float2*)(Am + r0 * 10 + 10 + i);
        float2 b0 = *(const float2*)(Bm + i * 10 + c0);
        float2 b1 = *(const float2*)(Bm + (i + 1) * 10 + c0);
        o00 = fmaf(a0.x, b0.x, o00); o00 = fmaf(a0.y, b1.x, o00);
        o01 = fmaf(a0.x, b0.y, o01); o01 = fmaf(a0.y, b1.y, o01);
        o10 = fmaf(a1.x, b0.x, o10); o10 = fmaf(a1.y, b1.x, o10);
        o11 = fmaf(a1.x, b0.y, o11); o11 = fmaf(a1.y, b1.y, o11);
    }
}
__device__ __forceinline__ void cst22(float* __restrict__ Bm, int r0, int c0,
                                      float v00, float v01, float v10, float v11) {
    *(float2*)(Bm + r0 * 10 + c0)       = make_float2(v00, v01);
    *(float2*)(Bm + (r0 + 1) * 10 + c0) = make_float2(v10, v11);
}

__device__ __forceinline__ void combine_run(const float* __restrict__ src,
                                            float* __restrict__ dst,
                                            float* Ac0, float* Ac1, float* Pb,
                                            int lane, int cntp) {
    bool act = lane < 25;
    int l  = act ? lane : 24;
    int j2 = l / 5, k2 = l % 5;
    int r0 = 2 * j2, c0 = 2 * k2;

    if (act) *(float4*)(Ac0 + lane * 4) = *(const float4*)(src + lane * 4);
    __syncwarp();

    float* cur = Ac0;
    float* nxt = Ac1;
    for (int p = 1; p < cntp; ++p) {
        if (act) *(float4*)(Pb + lane * 4) = *(const float4*)(src + p * 100 + lane * 4);
        __syncwarp();
        float o00, o01, o10, o11;
        cmm22(cur, Pb, r0, c0, o00, o01, o10, o11);
        if (act) cst22(nxt, r0, c0, o00, o01, o10, o11);
        __syncwarp();
        float* tmp = cur; cur = nxt; nxt = tmp;
    }
    if (act) *(float4*)(dst + lane * 4) = *(const float4*)(cur + lane * 4);
}

__global__ void __launch_bounds__(128) combineA() {
    __shared__ __align__(16) float sm[WPB][3][100];
    int warp = threadIdx.x >> 5, lane = threadIdx.x & 31;
    int w = blockIdx.x * WPB + warp;          // [0, 2048)
    int chain = w >> 4, g = w & 15;
    combine_run(g_part + ((size_t)chain * NCHUNK + g * 8) * 100,
                g_part2 + ((size_t)chain * 16 + g) * 100,
                sm[warp][0], sm[warp][1], sm[warp][2], lane, 8);
}

__global__ void __launch_bounds__(128) combineB(float* __restrict__ out) {
    __shared__ __align__(16) float sm[WPB][3][100];
    int warp = threadIdx.x >> 5, lane = threadIdx.x & 31;
    int chain = blockIdx.x * WPB + warp;      // [0, 128)
    combine_run(g_part2 + (size_t)chain * 16 * 100,
                out + (size_t)chain * 100,
                sm[warp][0], sm[warp][1], sm[warp][2], lane, 16);
}

extern "C" void kernel_launch(void* const* d_in, const int* in_sizes, int n_in,
                              void* d_out, int out_size) {
    const float* x = (const float*)d_in[0];
    const float* A = (const float*)d_in[1];
    if (n_in >= 2 && in_sizes[0] < in_sizes[1]) {
        const float* t = x; x = A; A = t;
    }

    step_kernel<<<NWARPS / WPB, 128>>>(x, A);   // 4096 blocks
    combineA<<<2048 / WPB, 128>>>();            // 512 blocks
    combineB<<<128 / WPB, 128>>>((float*)d_out);// 32 blocks
}

// round 11
// speedup vs baseline: 1.0205x; 1.0205x over previous
#include <cuda_runtime.h>

#define N_B    64
#define T_LEN  2048
#define IN_D   8
#define C_CH   2
#define STEPS  2047
#define LCHUNK 16
#define NCHUNK 128           // 128*16 = 2048 >= 2047
#define WPB    4
#define NCHAIN (N_B * C_CH)          // 128
#define NJOBS  (NCHAIN * NCHUNK)     // 16384 chunk-jobs
#define NWARPS (NJOBS / 2)           // 8192 warps, 2 jobs each
#define FULLM  0xffffffffu

__device__ __align__(16) float g_part [NJOBS * 100];
__device__ __align__(16) float g_part2[NCHAIN * 8 * 100];

// ---------------------------------------------------------------------------
// Kernel 1: one warp per (chain, chunk-pair). Each warp advances TWO
// independent 16-step chunks of the same chain, phase-interleaved, so the
// 26-cycle SHFL latency of one job is hidden by the other job's issue.
// Order-7 Taylor expm of skew G; all tiles register-distributed
// (lane l<25 owns 2x2 tile (j2=l/5, k2=l%5)); exchanges via __shfl_sync.
// Steps beyond the chain end use dx=0 => E=I exactly (uniform trip count).
// ---------------------------------------------------------------------------
__global__ void __launch_bounds__(128) step_kernel(const float* __restrict__ x,
                                                   const float* __restrict__ A) {
    __shared__ float sk[C_CH * IN_D * 100];
    __shared__ float xs[WPB][2][(LCHUNK + 1) * IN_D];
    __shared__ __align__(16) float dxs[WPB][2][LCHUNK * IN_D];

    int tid = threadIdx.x;

    // skew = A - A^T
    for (int idx = tid; idx < C_CH * IN_D * 100; idx += 128) {
        int jk = idx % 100, ci = idx / 100;
        int j = jk / 10, k = jk % 10;
        sk[idx] = A[ci * 100 + j * 10 + k] - A[ci * 100 + k * 10 + j];
    }

    int warp = tid >> 5, lane = tid & 31;
    int w     = blockIdx.x * WPB + warp;     // [0, 8192)
    int q     = w & 63;                      // chunk pair: q and q+64
    int chain = w >> 6;
    int c     = chain & 1;
    int n     = chain >> 1;

    int t0j[2]    = {q * LCHUNK, (q + 64) * LCHUNK};
    int nstepsj[2];
#pragma unroll
    for (int j = 0; j < 2; ++j) {
        nstepsj[j] = min(LCHUNK, STEPS - t0j[j]);
        const float* xp = x + ((size_t)n * T_LEN + t0j[j]) * IN_D;
        float* xw = xs[warp][j];
        int cnt = (nstepsj[j] + 1) * IN_D;
        for (int idx = lane; idx < cnt; idx += 32) xw[idx] = xp[idx];
    }
    __syncthreads();                          // sk + xw ready

#pragma unroll
    for (int j = 0; j < 2; ++j) {
        const float* xw = xs[warp][j];
        float* dxp = dxs[warp][j];
        int lim = nstepsj[j] * IN_D;
        for (int idx = lane; idx < LCHUNK * IN_D; idx += 32)
            dxp[idx] = (idx < lim) ? (xw[idx + IN_D] - xw[idx]) : 0.f;
    }
    __syncwarp();

    bool act = lane < 25;
    int l  = act ? lane : 24;
    int j2 = l / 5, k2 = l % 5;
    int r0 = 2 * j2, c0 = 2 * k2;
    float dI = (j2 == k2) ? 1.f : 0.f;

    // skew tiles -> registers (shared by both jobs: same chain/channel)
    const float* skc = sk + c * IN_D * 100;
    float ska[IN_D][4];
#pragma unroll
    for (int i = 0; i < IN_D; ++i) {
        float2 a0 = *(const float2*)(skc + i * 100 + r0 * 10 + c0);
        float2 a1 = *(const float2*)(skc + i * 100 + r0 * 10 + 10 + c0);
        ska[i][0] = a0.x; ska[i][1] = a0.y; ska[i][2] = a1.x; ska[i][3] = a1.y;
    }

    const float c2 = 0.5f,      c4 = 1.f / 24.f,  c6 = 1.f / 720.f;
    const float s2 = 1.f / 6.f, s4 = 1.f / 120.f, s6 = 1.f / 5040.f;

    float ac00[2], ac01[2], ac10[2], ac11[2];
#pragma unroll
    for (int j = 0; j < 2; ++j) { ac00[j] = dI; ac01[j] = 0.f; ac10[j] = 0.f; ac11[j] = dI; }

    float Gr0[2][10], Gr1[2][10], Wr0[2][10], Wr1[2][10];
    float g00[2], g01[2], g10[2], g11[2];
    float w00[2], w01[2], w10[2], w11[2];
    float C00[2], C01[2], C10[2], C11[2];
    float S00[2], S01[2], S10[2], S11[2];
    float e00[2], e01[2], e10[2], e11[2];

    for (int t = 0; t < LCHUNK; ++t) {
        // ---- G tiles ----
#pragma unroll
        for (int j = 0; j < 2; ++j) {
            const float* d = dxs[warp][j] + t * IN_D;
            float4 dA4 = *(const float4*)(d);
            float4 dB4 = *(const float4*)(d + 4);
            float dv[8] = {dA4.x, dA4.y, dA4.z, dA4.w, dB4.x, dB4.y, dB4.z, dB4.w};
            float a = 0.f, b = 0.f, cc = 0.f, dd = 0.f;
#pragma unroll
            for (int i = 0; i < 8; ++i) {
                a = fmaf(dv[i], ska[i][0], a); b  = fmaf(dv[i], ska[i][1], b);
                cc = fmaf(dv[i], ska[i][2], cc); dd = fmaf(dv[i], ska[i][3], dd);
            }
            g00[j] = a; g01[j] = b; g10[j] = cc; g11[j] = dd;
        }

        // ---- G strips ----
#pragma unroll
        for (int j = 0; j < 2; ++j)
#pragma unroll
            for (int k = 0; k < 5; ++k) {
                int src = j2 * 5 + k;
                Gr0[j][2*k]   = __shfl_sync(FULLM, g00[j], src);
                Gr0[j][2*k+1] = __shfl_sync(FULLM, g01[j], src);
                Gr1[j][2*k]   = __shfl_sync(FULLM, g10[j], src);
                Gr1[j][2*k+1] = __shfl_sync(FULLM, g11[j], src);
            }

        // ---- W = G@G ----
#pragma unroll
        for (int j = 0; j < 2; ++j) {
            float o00 = 0.f, o01 = 0.f, o10 = 0.f, o11 = 0.f;
#pragma unroll
            for (int i = 0; i < 5; ++i) {
                int src = i * 5 + k2;
                float b00 = __shfl_sync(FULLM, g00[j], src);
                float b01 = __shfl_sync(FULLM, g01[j], src);
                float b10 = __shfl_sync(FULLM, g10[j], src);
                float b11 = __shfl_sync(FULLM, g11[j], src);
                float a00 = Gr0[j][2*i], a01 = Gr0[j][2*i+1];
                float a10 = Gr1[j][2*i], a11 = Gr1[j][2*i+1];
                o00 = fmaf(a00, b00, o00); o00 = fmaf(a01, b10, o00);
                o01 = fmaf(a00, b01, o01); o01 = fmaf(a01, b11, o01);
                o10 = fmaf(a10, b00, o10); o10 = fmaf(a11, b10, o10);
                o11 = fmaf(a10, b01, o11); o11 = fmaf(a11, b11, o11);
            }
            w00[j] = o00; w01[j] = o01; w10[j] = o10; w11[j] = o11;
        }

        // ---- W strips ----
#pragma unroll
        for (int j = 0; j < 2; ++j)
#pragma unroll
            for (int k = 0; k < 5; ++k) {
                int src = j2 * 5 + k;
                Wr0[j][2*k]   = __shfl_sync(FULLM, w00[j], src);
                Wr0[j][2*k+1] = __shfl_sync(FULLM, w01[j], src);
                Wr1[j][2*k]   = __shfl_sync(FULLM, w10[j], src);
                Wr1[j][2*k+1] = __shfl_sync(FULLM, w11[j], src);
            }

        // ---- P = W@W ; C,S low-order folds ----
#pragma unroll
        for (int j = 0; j < 2; ++j) {
            float o00 = 0.f, o01 = 0.f, o10 = 0.f, o11 = 0.f;
#pragma unroll
            for (int i = 0; i < 5; ++i) {
                int src = i * 5 + k2;
                float b00 = __shfl_sync(FULLM, w00[j], src);
                float b01 = __shfl_sync(FULLM, w01[j], src);
                float b10 = __shfl_sync(FULLM, w10[j], src);
                float b11 = __shfl_sync(FULLM, w11[j], src);
                float a00 = Wr0[j][2*i], a01 = Wr0[j][2*i+1];
                float a10 = Wr1[j][2*i], a11 = Wr1[j][2*i+1];
                o00 = fmaf(a00, b00, o00); o00 = fmaf(a01, b10, o00);
                o01 = fmaf(a00, b01, o01); o01 = fmaf(a01, b11, o01);
                o10 = fmaf(a10, b00, o10); o10 = fmaf(a11, b10, o10);
                o11 = fmaf(a10, b01, o11); o11 = fmaf(a11, b11, o11);
            }
            C00[j] = fmaf(c4, o00, fmaf(c2, w00[j], dI));
            C01[j] = fmaf(c4, o01, c2 * w01[j]);
            C10[j] = fmaf(c4, o10, c2 * w10[j]);
            C11[j] = fmaf(c4, o11, fmaf(c2, w11[j], dI));
            S00[j] = fmaf(s4, o00, fmaf(s2, w00[j], dI));
            S01[j] = fmaf(s4, o01, s2 * w01[j]);
            S10[j] = fmaf(s4, o10, s2 * w10[j]);
            S11[j] = fmaf(s4, o11, fmaf(s2, w11[j], dI));
            // reuse g-regs to carry P tile for the V6 gather
            g00[j] = o00; g01[j] = o01; g10[j] = o10; g11[j] = o11;
        }

        // ---- V6 = W@P ; fold into C,S ----
#pragma unroll
        for (int j = 0; j < 2; ++j) {
            float o00 = 0.f, o01 = 0.f, o10 = 0.f, o11 = 0.f;
#pragma unroll
            for (int i = 0; i < 5; ++i) {
                int src = i * 5 + k2;
                float b00 = __shfl_sync(FULLM, g00[j], src);
                float b01 = __shfl_sync(FULLM, g01[j], src);
                float b10 = __shfl_sync(FULLM, g10[j], src);
                float b11 = __shfl_sync(FULLM, g11[j], src);
                float a00 = Wr0[j][2*i], a01 = Wr0[j][2*i+1];
                float a10 = Wr1[j][2*i], a11 = Wr1[j][2*i+1];
                o00 = fmaf(a00, b00, o00); o00 = fmaf(a01, b10, o00);
                o01 = fmaf(a00, b01, o01); o01 = fmaf(a01, b11, o01);
                o10 = fmaf(a10, b00, o10); o10 = fmaf(a11, b10, o10);
                o11 = fmaf(a10, b01, o11); o11 = fmaf(a11, b11, o11);
            }
            C00[j] = fmaf(c6, o00, C00[j]); C01[j] = fmaf(c6, o01, C01[j]);
            C10[j] = fmaf(c6, o10, C10[j]); C11[j] = fmaf(c6, o11, C11[j]);
            S00[j] = fmaf(s6, o00, S00[j]); S01[j] = fmaf(s6, o01, S01[j]);
            S10[j] = fmaf(s6, o10, S10[j]); S11[j] = fmaf(s6, o11, S11[j]);
        }

        // ---- E = C + G@S ----
#pragma unroll
        for (int j = 0; j < 2; ++j) {
            float o00 = C00[j], o01 = C01[j], o10 = C10[j], o11 = C11[j];
#pragma unroll
            for (int i = 0; i < 5; ++i) {
                int src = i * 5 + k2;
                float b00 = __shfl_sync(FULLM, S00[j], src);
                float b01 = __shfl_sync(FULLM, S01[j], src);
                float b10 = __shfl_sync(FULLM, S10[j], src);
                float b11 = __shfl_sync(FULLM, S11[j], src);
                float a00 = Gr0[j][2*i], a01 = Gr0[j][2*i+1];
                float a10 = Gr1[j][2*i], a11 = Gr1[j][2*i+1];
                o00 = fmaf(a00, b00, o00); o00 = fmaf(a01, b10, o00);
                o01 = fmaf(a00, b01, o01); o01 = fmaf(a01, b11, o01);
                o10 = fmaf(a10, b00, o10); o10 = fmaf(a11, b10, o10);
                o11 = fmaf(a10, b01, o11); o11 = fmaf(a11, b11, o11);
            }
            e00[j] = o00; e01[j] = o01; e10[j] = o10; e11[j] = o11;
        }

        // ---- Acc = Acc @ E ----
#pragma unroll
        for (int j = 0; j < 2; ++j) {
            float o00 = 0.f, o01 = 0.f, o10 = 0.f, o11 = 0.f;
#pragma unroll
            for (int i = 0; i < 5; ++i) {
                int sa = j2 * 5 + i;
                int sb = i * 5 + k2;
                float a00 = __shfl_sync(FULLM, ac00[j], sa);
                float a01 = __shfl_sync(FULLM, ac01[j], sa);
                float a10 = __shfl_sync(FULLM, ac10[j], sa);
                float a11 = __shfl_sync(FULLM, ac11[j], sa);
                float b00 = __shfl_sync(FULLM, e00[j], sb);
                float b01 = __shfl_sync(FULLM, e01[j], sb);
                float b10 = __shfl_sync(FULLM, e10[j], sb);
                float b11 = __shfl_sync(FULLM, e11[j], sb);
                o00 = fmaf(a00, b00, o00); o00 = fmaf(a01, b10, o00);
                o01 = fmaf(a00, b01, o01); o01 = fmaf(a01, b11, o01);
                o10 = fmaf(a10, b00, o10); o10 = fmaf(a11, b10, o10);
                o11 = fmaf(a10, b01, o11); o11 = fmaf(a11, b11, o11);
            }
            ac00[j] = o00; ac01[j] = o01; ac10[j] = o10; ac11[j] = o11;
        }
    }

    if (act) {
#pragma unroll
        for (int j = 0; j < 2; ++j) {
            int job = chain * NCHUNK + (q + j * 64) * 1;
            float* pp = g_part + (size_t)(chain * NCHUNK + q + j * 64) * 100;
            (void)job;
            *(float2*)(pp + r0 * 10 + c0)       = make_float2(ac00[j], ac01[j]);
            *(float2*)(pp + (r0 + 1) * 10 + c0) = make_float2(ac10[j], ac11[j]);
        }
    }
}

// ---------------------------------------------------------------------------
// Tree combine: 128 partials -> 8 (combineA, 16-way, 1024 warps)
//                           -> 1 (combineB, 8-way, 128 warps)
// ---------------------------------------------------------------------------
__device__ __forceinline__ void cmm22(const float* __restrict__ Am,
                                      const float* __restrict__ Bm,
                                      int r0, int c0,
                                      float& o00, float& o01, float& o10, float& o11) {
    o00 = 0.f; o01 = 0.f; o10 = 0.f; o11 = 0.f;
#pragma unroll
    for (int i = 0; i < 10; i += 2) {
        float2 a0 = *(const float2*)(Am + r0 * 10 + i);
        float2 a1 = *(const float2*)(Am + r0 * 10 + 10 + i);
        float2 b0 = *(const float2*)(Bm + i * 10 + c0);
        float2 b1 = *(const float2*)(Bm + (i + 1) * 10 + c0);
        o00 = fmaf(a0.x, b0.x, o00); o00 = fmaf(a0.y, b1.x, o00);
        o01 = fmaf(a0.x, b0.y, o01); o01 = fmaf(a0.y, b1.y, o01);
        o10 = fmaf(a1.x, b0.x, o10); o10 = fmaf(a1.y, b1.x, o10);
        o11 = fmaf(a1.x, b0.y, o11); o11 = fmaf(a1.y, b1.y, o11);
    }
}
__device__ __forceinline__ void cst22(float* __restrict__ Bm, int r0, int c0,
                                      float v00, float v01, float v10, float v11) {
    *(float2*)(Bm + r0 * 10 + c0)       = make_float2(v00, v01);
    *(float2*)(Bm + (r0 + 1) * 10 + c0) = make_float2(v10, v11);
}

__device__ __forceinline__ void combine_run(const float* __restrict__ src,
                                            float* __restrict__ dst,
                                            float* Ac0, float* Ac1, float* Pb,
                                            int lane, int cntp) {
    bool act = lane < 25;
    int l  = act ? lane : 24;
    int j2 = l / 5, k2 = l % 5;
    int r0 = 2 * j2, c0 = 2 * k2;

    if (act) *(float4*)(Ac0 + lane * 4) = *(const float4*)(src + lane * 4);
    __syncwarp();

    float* cur = Ac0;
    float* nxt = Ac1;
    for (int p = 1; p < cntp; ++p) {
        if (act) *(float4*)(Pb + lane * 4) = *(const float4*)(src + p * 100 + lane * 4);
        __syncwarp();
        float o00, o01, o10, o11;
        cmm22(cur, Pb, r0, c0, o00, o01, o10, o11);
        if (act) cst22(nxt, r0, c0, o00, o01, o10, o11);
        __syncwarp();
        float* tmp = cur; cur = nxt; nxt = tmp;
    }
    if (act) *(float4*)(dst + lane * 4) = *(const float4*)(cur + lane * 4);
}

__global__ void __launch_bounds__(128) combineA() {
    __shared__ __align__(16) float sm[WPB][3][100];
    int warp = threadIdx.x >> 5, lane = threadIdx.x & 31;
    int w = blockIdx.x * WPB + warp;          // [0, 1024)
    int chain = w >> 3, g = w & 7;
    combine_run(g_part + ((size_t)chain * NCHUNK + g * 16) * 100,
                g_part2 + ((size_t)chain * 8 + g) * 100,
                sm[warp][0], sm[warp][1], sm[warp][2], lane, 16);
}

__global__ void __launch_bounds__(128) combineB(float* __restrict__ out) {
    __shared__ __align__(16) float sm[WPB][3][100];
    int warp = threadIdx.x >> 5, lane = threadIdx.x & 31;
    int chain = blockIdx.x * WPB + warp;      // [0, 128)
    combine_run(g_part2 + (size_t)chain * 8 * 100,
                out + (size_t)chain * 100,
                sm[warp][0], sm[warp][1], sm[warp][2], lane, 8);
}

extern "C" void kernel_launch(void* const* d_in, const int* in_sizes, int n_in,
                              void* d_out, int out_size) {
    const float* x = (const float*)d_in[0];
    const float* A = (const float*)d_in[1];
    if (n_in >= 2 && in_sizes[0] < in_sizes[1]) {
        const float* t = x; x = A; A = t;
    }

    step_kernel<<<NWARPS / WPB, 128>>>(x, A);   // 2048 blocks
    combineA<<<1024 / WPB, 128>>>();            // 256 blocks
    combineB<<<128 / WPB, 128>>>((float*)d_out);// 32 blocks
}